// round 8
// baseline (speedup 1.0000x reference)
#include <cuda_runtime.h>
#include <math.h>

// EntropyBottleneck — prep + fast stream, PDL-overlapped.
//
// Structure exploited (verified at runtime per channel):
//   * every m{i} constant-filled -> rank-1 layers
//   * every t{i} == 0            -> tanh gating vanishes
// => lower = alpha*x + beta_l, upper = alpha*x + beta_u per channel
//    (beta_l/beta_u fold the +-0.5 shift).
//
// eb_prep (grid=C): folds {flag, alpha, beta_l, beta_u}; publishes g_ab and
//   TRIGGERS the dependent eb_fast launch immediately, then (only if the
//   structure fails for a channel — never on this problem) runs the full MLP
//   for that channel.
// eb_fast: launched with programmatic stream serialization — starts while
//   prep runs, issues its input loads, then griddepsyncs before touching g_ab.

__device__ float4 g_ab[256];   // {flag, alpha, beta_l, beta_u}

__device__ __forceinline__ float softplus_f(float v) {
    if (v > 20.0f) return v;
    if (v < -20.0f) return expf(v);
    return log1pf(expf(v));
}

__device__ __forceinline__ float sigmoid_fast(float x) {
    float e = __expf(-x);
    return __fdividef(1.0f, 1.0f + e);
}

// ---------------------------------------------------------------------------
// Prep: one block per channel, 256 threads, shared staging.
// ---------------------------------------------------------------------------
__global__ __launch_bounds__(256) void eb_prep(
    const float* __restrict__ in, float* __restrict__ out,
    const float* __restrict__ m0, const float* __restrict__ b0, const float* __restrict__ t0,
    const float* __restrict__ m1, const float* __restrict__ b1, const float* __restrict__ t1,
    const float* __restrict__ m2, const float* __restrict__ b2, const float* __restrict__ t2,
    const float* __restrict__ m3, const float* __restrict__ b3, const float* __restrict__ t3,
    const float* __restrict__ m4, const float* __restrict__ b4,
    int N, long long CN)
{
    const int c   = blockIdx.x;
    const int tid = threadIdx.x;

    __shared__ float sW0[3], sB0[3], sT0[3];
    __shared__ float sW[3][9], sBv[3][3], sT[3][3];
    __shared__ float sW4[3], sB4;
    __shared__ int   sFlag;

    if (tid == 0) sFlag = 1;
    __syncthreads();

    if (tid < 3) {
        float v = m0[c * 3 + tid];
        if (v != m0[c * 3]) atomicAnd(&sFlag, 0);
        sW0[tid] = softplus_f(v);
        sB0[tid] = b0[c * 3 + tid];
        float tv = t0[c * 3 + tid];
        if (tv != 0.0f) atomicAnd(&sFlag, 0);
        sT0[tid] = tanhf(tv);
    } else if (tid < 30) {
        int l = (tid - 3) / 9, j = (tid - 3) % 9;
        const float* m = (l == 0) ? m1 : (l == 1) ? m2 : m3;
        float v = m[c * 9 + j];
        if (v != m[c * 9]) atomicAnd(&sFlag, 0);
        sW[l][j] = softplus_f(v);
    } else if (tid < 33) {
        int j = tid - 30;
        float v = m4[c * 3 + j];
        if (v != m4[c * 3]) atomicAnd(&sFlag, 0);
        sW4[j] = softplus_f(v);
    } else if (tid < 42) {
        int l = (tid - 33) / 3, j = (tid - 33) % 3;
        const float* b = (l == 0) ? b1 : (l == 1) ? b2 : b3;
        const float* t = (l == 0) ? t1 : (l == 1) ? t2 : t3;
        sBv[l][j] = b[c * 3 + j];
        float tv = t[c * 3 + j];
        if (tv != 0.0f) atomicAnd(&sFlag, 0);
        sT[l][j] = tanhf(tv);
    } else if (tid == 42) {
        sB4 = b4[c];
    }
    __syncthreads();

    if (tid == 0) {
        float alpha = sW0[0];
        alpha *= (sW[0][0] + sW[0][1] + sW[0][2]);
        alpha *= (sW[1][0] + sW[1][1] + sW[1][2]);
        alpha *= (sW[2][0] + sW[2][1] + sW[2][2]);
        alpha *= (sW4[0] + sW4[1] + sW4[2]);

        float y0 = sB0[0], y1 = sB0[1], y2 = sB0[2];
        #pragma unroll
        for (int l = 0; l < 3; l++) {
            float z0 = sW[l][0] * y0 + sW[l][1] * y1 + sW[l][2] * y2 + sBv[l][0];
            float z1 = sW[l][3] * y0 + sW[l][4] * y1 + sW[l][5] * y2 + sBv[l][1];
            float z2 = sW[l][6] * y0 + sW[l][7] * y1 + sW[l][8] * y2 + sBv[l][2];
            y0 = z0; y1 = z1; y2 = z2;
        }
        float beta = sW4[0] * y0 + sW4[1] * y1 + sW4[2] * y2 + sB4;
        float hb = 0.5f * alpha;
        g_ab[c] = make_float4(sFlag ? 1.0f : 0.0f, alpha, beta - hb, beta + hb);
        __threadfence();
    }
    __syncthreads();

#if defined(__CUDA_ARCH__) && __CUDA_ARCH__ >= 900
    // Release the dependent eb_fast launch as soon as params are published.
    cudaTriggerProgrammaticLaunchCompletion();
#endif

    if (sFlag) return;   // fast kernel handles this channel

    // ---- Safety-net fallback: full MLP for this channel (disjoint from the
    //      channels eb_fast writes; never taken on this problem's inputs). --
    const long long base = (long long)c * N;
    float* lik = out + base;
    float* low = out + CN + base;
    float* upp = out + 2 * CN + base;
    for (int e = tid; e < N; e += 256) {
        float x = in[base + e];
        float r2[2];
        #pragma unroll
        for (int s = 0; s < 2; s++) {
            float xi = x + (s ? 0.5f : -0.5f);
            float y0 = fmaf(sW0[0], xi, sB0[0]);
            float y1 = fmaf(sW0[1], xi, sB0[1]);
            float y2 = fmaf(sW0[2], xi, sB0[2]);
            y0 = fmaf(sT0[0], tanhf(y0), y0);
            y1 = fmaf(sT0[1], tanhf(y1), y1);
            y2 = fmaf(sT0[2], tanhf(y2), y2);
            #pragma unroll
            for (int l = 0; l < 3; l++) {
                float z0 = sW[l][0] * y0 + sW[l][1] * y1 + sW[l][2] * y2 + sBv[l][0];
                float z1 = sW[l][3] * y0 + sW[l][4] * y1 + sW[l][5] * y2 + sBv[l][1];
                float z2 = sW[l][6] * y0 + sW[l][7] * y1 + sW[l][8] * y2 + sBv[l][2];
                y0 = fmaf(sT[l][0], tanhf(z0), z0);
                y1 = fmaf(sT[l][1], tanhf(z1), z1);
                y2 = fmaf(sT[l][2], tanhf(z2), z2);
            }
            r2[s] = sW4[0] * y0 + sW4[1] * y1 + sW4[2] * y2 + sB4;
        }
        lik[e] = 1.0f / (1.0f + expf(-r2[1])) - 1.0f / (1.0f + expf(-r2[0]));
        low[e] = r2[0];
        upp[e] = r2[1];
    }
}

// ---------------------------------------------------------------------------
// Fast path: pure streaming. Input loads issued BEFORE griddepsync so the
// first wave's DRAM latency overlaps prep + launch.
// ---------------------------------------------------------------------------
#define FAST_EPB 4096   // 256 threads * 4 float4

__global__ __launch_bounds__(256, 6) void eb_fast(
    const float* __restrict__ in, float* __restrict__ out, int N, long long CN)
{
    const int c = blockIdx.y;
    const long long base = (long long)c * N;
    const int blk = blockIdx.x * FAST_EPB;

    const float* src = in + base;
    float* lik = out + base;
    float* low = out + CN + base;
    float* upp = out + 2 * CN + base;

    const bool interior = (blk + FAST_EPB <= N);
    const int e0 = blk + threadIdx.x * 4;
    const int e1 = e0 + 1024;

    float4 x0, x1;
    if (interior) {                       // prefetch BEFORE the dependency sync
        x0 = __ldcs((const float4*)(src + e0));
        x1 = __ldcs((const float4*)(src + e1));
    }

#if defined(__CUDA_ARCH__) && __CUDA_ARCH__ >= 900
    cudaGridDependencySynchronize();
#endif

    const float4 fab = g_ab[c];           // {flag, alpha, beta_l, beta_u}
    if (fab.x == 0.0f) return;            // prep handled this channel
    const float alpha = fab.y, bl = fab.z, bu = fab.w;

    if (interior) {
        #pragma unroll
        for (int i = 0; i < 2; i++) {
            if (i) {                      // second pair of loads
                x0 = __ldcs((const float4*)(src + e0 + 2048));
                x1 = __ldcs((const float4*)(src + e1 + 2048));
            }
            const int a0 = e0 + i * 2048;
            const int a1 = e1 + i * 2048;

            float4 l0, u0, k0;
            l0.x = fmaf(alpha, x0.x, bl); u0.x = fmaf(alpha, x0.x, bu);
            l0.y = fmaf(alpha, x0.y, bl); u0.y = fmaf(alpha, x0.y, bu);
            l0.z = fmaf(alpha, x0.z, bl); u0.z = fmaf(alpha, x0.z, bu);
            l0.w = fmaf(alpha, x0.w, bl); u0.w = fmaf(alpha, x0.w, bu);
            k0.x = sigmoid_fast(u0.x) - sigmoid_fast(l0.x);
            k0.y = sigmoid_fast(u0.y) - sigmoid_fast(l0.y);
            k0.z = sigmoid_fast(u0.z) - sigmoid_fast(l0.z);
            k0.w = sigmoid_fast(u0.w) - sigmoid_fast(l0.w);
            __stcs((float4*)(lik + a0), k0);
            __stcs((float4*)(low + a0), l0);
            __stcs((float4*)(upp + a0), u0);

            float4 l1, u1, k1;
            l1.x = fmaf(alpha, x1.x, bl); u1.x = fmaf(alpha, x1.x, bu);
            l1.y = fmaf(alpha, x1.y, bl); u1.y = fmaf(alpha, x1.y, bu);
            l1.z = fmaf(alpha, x1.z, bl); u1.z = fmaf(alpha, x1.z, bu);
            l1.w = fmaf(alpha, x1.w, bl); u1.w = fmaf(alpha, x1.w, bu);
            k1.x = sigmoid_fast(u1.x) - sigmoid_fast(l1.x);
            k1.y = sigmoid_fast(u1.y) - sigmoid_fast(l1.y);
            k1.z = sigmoid_fast(u1.z) - sigmoid_fast(l1.z);
            k1.w = sigmoid_fast(u1.w) - sigmoid_fast(l1.w);
            __stcs((float4*)(lik + a1), k1);
            __stcs((float4*)(low + a1), l1);
            __stcs((float4*)(upp + a1), u1);
        }
    } else {
        #pragma unroll
        for (int i = 0; i < 4; i++) {
            int s = blk + i * 1024 + threadIdx.x * 4;
            int lim = min(s + 4, N);
            for (int q = s; q < lim; q++) {
                float x = src[q];
                float l = fmaf(alpha, x, bl);
                float u = fmaf(alpha, x, bu);
                lik[q] = sigmoid_fast(u) - sigmoid_fast(l);
                low[q] = l;
                upp[q] = u;
            }
        }
    }
}

// ---------------------------------------------------------------------------
// Host launcher
// ---------------------------------------------------------------------------
extern "C" void kernel_launch(void* const* d_in, const int* in_sizes, int n_in,
                              void* d_out, int out_size)
{
    // Input-order detection.
    // Order A (dict order): inputs, m0,b0,t0, m1,b1,t1, m2,b2,t2, m3,b3,t3, m4,b4
    // Order B (signature):  inputs, m0..m4, b0..b4, t0..t3
    int im[5], ib[5], it[4];
    if (n_in >= 15 && in_sizes[2] == in_sizes[1]) {
        im[0] = 1;  ib[0] = 2;  it[0] = 3;
        im[1] = 4;  ib[1] = 5;  it[1] = 6;
        im[2] = 7;  ib[2] = 8;  it[2] = 9;
        im[3] = 10; ib[3] = 11; it[3] = 12;
        im[4] = 13; ib[4] = 14;
    } else {
        im[0] = 1; im[1] = 2; im[2] = 3; im[3] = 4; im[4] = 5;
        ib[0] = 6; ib[1] = 7; ib[2] = 8; ib[3] = 9; ib[4] = 10;
        it[0] = 11; it[1] = 12; it[2] = 13; it[3] = 14;
    }

    const float* in = (const float*)d_in[0];
    float* out = (float*)d_out;

    int C = in_sizes[ib[4]];          // b4 is (C,1,1)
    if (C <= 0 || C > 256) C = 192;
    int N = in_sizes[0] / C;
    long long CN = (long long)C * N;

    eb_prep<<<C, 256>>>(
        in, out,
        (const float*)d_in[im[0]], (const float*)d_in[ib[0]], (const float*)d_in[it[0]],
        (const float*)d_in[im[1]], (const float*)d_in[ib[1]], (const float*)d_in[it[1]],
        (const float*)d_in[im[2]], (const float*)d_in[ib[2]], (const float*)d_in[it[2]],
        (const float*)d_in[im[3]], (const float*)d_in[ib[3]], (const float*)d_in[it[3]],
        (const float*)d_in[im[4]], (const float*)d_in[ib[4]],
        N, CN);

    dim3 gfast((N + FAST_EPB - 1) / FAST_EPB, C);

    // Programmatic dependent launch: eb_fast overlaps eb_prep, released by
    // the in-kernel trigger. Plain launch as fallback if unsupported.
    cudaLaunchConfig_t cfg = {};
    cfg.gridDim  = gfast;
    cfg.blockDim = dim3(256, 1, 1);
    cfg.dynamicSmemBytes = 0;
    cfg.stream = 0;
    cudaLaunchAttribute attr[1];
    attr[0].id = cudaLaunchAttributeProgrammaticStreamSerialization;
    attr[0].val.programmaticStreamSerializationAllowed = 1;
    cfg.attrs = attr;
    cfg.numAttrs = 1;

    cudaError_t e = cudaLaunchKernelEx(&cfg, eb_fast, in, out, N, CN);
    if (e != cudaSuccess) {
        (void)cudaGetLastError();         // clear sticky error, fall back
        eb_fast<<<gfast, 256>>>(in, out, N, CN);
    }
}